// round 6
// baseline (speedup 1.0000x reference)
#include <cuda_runtime.h>
#include <cuda_bf16.h>
#include <cstddef>
#include <cstdint>

#define BB     128
#define TT     1024
#define FF     256
#define TPB    256   // one CTA per batch: thread = feature
#define TS     8     // timesteps per pipeline stage
#define STAGES 4     // smem pipeline depth
#define NSTG   (TT / TS)            // 128 stages
#define STAGE_FLOATS (TS * FF)      // 2048 floats (8 KB) per channel per stage
#define SMEM_BYTES (STAGES * STAGE_FLOATS * 2 * 4)   // 64 KB

__device__ __forceinline__ float tanh_approx(float x) {
    float y;
    asm("tanh.approx.f32 %0, %1;" : "=f"(y) : "f"(x));
    return y;
}

__device__ __forceinline__ void cp16(uint32_t smem_addr, const void* gptr) {
    asm volatile("cp.async.cg.shared.global [%0], [%1], 16;" :: "r"(smem_addr), "l"(gptr));
}

__global__ __launch_bounds__(TPB, 1)
void grud_main(
    const float* __restrict__ input,   // [B, 3, T, F]
    const float* __restrict__ x_mean,
    const float* __restrict__ w_xz, const float* __restrict__ w_hz, const float* __restrict__ w_mz,
    const float* __restrict__ w_xr, const float* __restrict__ w_hr, const float* __restrict__ w_mr,
    const float* __restrict__ w_xh, const float* __restrict__ w_hh, const float* __restrict__ w_mh,
    const float* __restrict__ b_z,  const float* __restrict__ b_r,  const float* __restrict__ b_h,
    const float* __restrict__ W_cls, const float* __restrict__ b_cls,
    float* __restrict__ out)
{
    extern __shared__ float smem[];
    // layout: sX = smem[0 .. STAGES*2048), sM = smem[STAGES*2048 .. 2*STAGES*2048)
    float* sX = smem;
    float* sM = smem + STAGES * STAGE_FLOATS;

    const int b   = blockIdx.x;
    const int tid = threadIdx.x;
    const int f   = tid;

    // sigmoid(p) = 0.5 + 0.5*tanh(0.5*p): pre-halve z/r coefficients.
    const float xm  = x_mean[f];
    const float wxz = 0.5f * w_xz[f], whz = 0.5f * w_hz[f], wmz = 0.5f * w_mz[f], bz = 0.5f * b_z[f];
    const float wxr = 0.5f * w_xr[f], whr = 0.5f * w_hr[f], wmr = 0.5f * w_mr[f], br = 0.5f * b_r[f];
    const float wxh = w_xh[f], wh2 = 0.5f * w_hh[f], wmh = w_mh[f], bh = b_h[f];

    const float* Xg = input + (size_t)b * 3 * TT * FF;   // channel 0
    const float* Mg = Xg + (size_t)TT * FF;              // channel 1

    // Per stage: 2 ch * 8 rows * 64 chunks(16B) = 1024 chunks, 4 per thread.
    // g = tid + i*256: ch = g>>9, row = (g&511)>>6, col = (g&63)*4.
    auto issue_stage = [&](int s) {
        const int buf = s & (STAGES - 1);
        const int t0  = s * TS;
#pragma unroll
        for (int i = 0; i < 4; i++) {
            const int g   = tid + i * TPB;
            const int ch  = g >> 9;
            const int row = (g & 511) >> 6;
            const int c4  = (g & 63) << 2;     // float index within 256-wide row
            const float* src = (ch ? Mg : Xg) + (size_t)(t0 + row) * FF + c4;
            float* dst = (ch ? sM : sX) + buf * STAGE_FLOATS + row * FF + c4;
            cp16((uint32_t)__cvta_generic_to_shared(dst), src);
        }
        asm volatile("cp.async.commit_group;");
    };

    issue_stage(0);
    issue_stage(1);
    issue_stage(2);

    float h = 0.0f;

    for (int s = 0; s < NSTG; s++) {
        const int buf = s & (STAGES - 1);
        asm volatile("cp.async.wait_group 2;");   // own groups <= s complete
        __syncthreads();                          // stage s visible block-wide;
                                                  // also: all reads of buf s-1 done
        if (s + 3 < NSTG) issue_stage(s + 3);     // overwrites buffer of s-1 (safe)

        // Batch this stage's 16 LDS, then run 8 recurrence steps.
        float xv[TS], mv[TS];
        const float* bx = sX + buf * STAGE_FLOATS + tid;
        const float* bm = sM + buf * STAGE_FLOATS + tid;
#pragma unroll
        for (int u = 0; u < TS; u++) { xv[u] = bx[u * FF]; mv[u] = bm[u * FF]; }

#pragma unroll
        for (int u = 0; u < TS; u++) {
            const float m  = mv[u];
            const float x  = fmaf(m, xv[u] - xm, xm);        // m*x + (1-m)*mean
            const float pz = fmaf(whz, h, fmaf(wxz, x, fmaf(wmz, m, bz)));
            const float pr = fmaf(whr, h, fmaf(wxr, x, fmaf(wmr, m, br)));
            const float ch = fmaf(wxh, x, fmaf(wmh, m, bh));
            const float a  = wh2 * h;                        // 0.5*whh*h
            const float tr = tanh_approx(pr);
            const float tz = tanh_approx(pz);
            const float ht = tanh_approx(fmaf(a, tr, a + ch));  // whh*r*h = a + a*tr
            const float z  = fmaf(0.5f, tz, 0.5f);
            const float ng = fmaf(-z, h, h);                 // (1-z)*h
            h = fmaf(z, ht, ng);
        }
    }

    // ---- fused classifier: full in-block reduction over 256 features ----
    float p0 = h * W_cls[f];
    float p1 = h * W_cls[FF + f];
#pragma unroll
    for (int o = 16; o > 0; o >>= 1) {
        p0 += __shfl_down_sync(0xffffffffu, p0, o);
        p1 += __shfl_down_sync(0xffffffffu, p1, o);
    }

    __syncthreads();          // done with pipeline smem; reuse it for partials
    float* s0 = smem;         // 8 warp partials each
    float* s1 = smem + 8;
    const int wid = tid >> 5;
    if ((tid & 31) == 0) { s0[wid] = p0; s1[wid] = p1; }
    __syncthreads();

    if (tid == 0) {
        float a0 = 0.0f, a1 = 0.0f;
#pragma unroll
        for (int w = 0; w < TPB / 32; w++) { a0 += s0[w]; a1 += s1[w]; }
        a0 += b_cls[0];
        a1 += b_cls[1];
        out[b * 2 + 0] = 1.0f / (1.0f + __expf(-a0));
        out[b * 2 + 1] = 1.0f / (1.0f + __expf(-a1));
    }
}

extern "C" void kernel_launch(void* const* d_in, const int* in_sizes, int n_in,
                              void* d_out, int out_size)
{
    const float* input  = (const float*)d_in[0];
    const float* x_mean = (const float*)d_in[1];
    const float* w_xz   = (const float*)d_in[2];
    const float* w_hz   = (const float*)d_in[3];
    const float* w_mz   = (const float*)d_in[4];
    const float* w_xr   = (const float*)d_in[5];
    const float* w_hr   = (const float*)d_in[6];
    const float* w_mr   = (const float*)d_in[7];
    const float* w_xh   = (const float*)d_in[8];
    const float* w_hh   = (const float*)d_in[9];
    const float* w_mh   = (const float*)d_in[10];
    const float* b_z    = (const float*)d_in[11];
    const float* b_r    = (const float*)d_in[12];
    const float* b_h    = (const float*)d_in[13];
    const float* W_cls  = (const float*)d_in[14];
    const float* b_cls  = (const float*)d_in[15];
    float* out = (float*)d_out;

    // Idempotent opt-in for 64 KB dynamic smem (host attr set, capture-safe).
    cudaFuncSetAttribute(grud_main, cudaFuncAttributeMaxDynamicSharedMemorySize, SMEM_BYTES);

    grud_main<<<BB, TPB, SMEM_BYTES>>>(input, x_mean,
                                       w_xz, w_hz, w_mz,
                                       w_xr, w_hr, w_mr,
                                       w_xh, w_hh, w_mh,
                                       b_z, b_r, b_h,
                                       W_cls, b_cls, out);
}